// round 13
// baseline (speedup 1.0000x reference)
#include <cuda_runtime.h>
#include <math.h>

#define BATCH 8
#define QLEN 256
#define KLEN 1024
#define DQ   256
#define DV   128
#define H    128
#define NKT  32          // max k-tiles (KLEN/32)

// Scratch (statically allocated device globals — no cudaMalloc).
__device__ float g_qh[BATCH * QLEN * H];                  // 1 MB
__device__ float g_kh[BATCH * KLEN * H];                  // 4 MB
__device__ float g_part[NKT * BATCH * QLEN * DV];         // 32 MB AV partials
__device__ float g_plsum[NKT * BATCH * QLEN];             // 256 KB row-sum partials
__device__ unsigned int g_ctr;                            // work-stealing counter

__device__ __forceinline__ float fast_tanh(float x) {
    float y;
    asm("tanh.approx.f32 %0, %1;" : "=f"(y) : "f"(x));
    return y;
}

// ---------------------------------------------------------------------------
// Kernel 1: fused projections qh = Q@Wq, kh = K@Wk.
// 32 output rows x 64 cols per block -> 640 blocks x 128 threads.
// 4x4 reg tile, double-buffered smem + register prefetch.
// ---------------------------------------------------------------------------
__global__ __launch_bounds__(128) void proj_kernel(
    const float* __restrict__ Qin, const float* __restrict__ Kin,
    const float* __restrict__ Wq,  const float* __restrict__ Wk)
{
    if (blockIdx.x == 0 && threadIdx.x == 0) g_ctr = 0;  // reset for fused

    __shared__ float Xs[2][32][36];
    __shared__ float Ws[2][32][64];

    int blk = blockIdx.x;
    const float* X; const float* W; float* Y; int r0, c0;
    if (blk < 128) { X = Qin; W = Wq; Y = g_qh; r0 = (blk >> 1) * 32; c0 = (blk & 1) * 64; }
    else { int bb = blk - 128; X = Kin; W = Wk; Y = g_kh; r0 = (bb >> 1) * 32; c0 = (bb & 1) * 64; }

    int tid = threadIdx.x;
    int tx = tid & 15;       // -> 4 cols at 4*tx
    int ty = tid >> 4;       // -> 4 rows at 4*ty

    float acc[4][4] = {};

    #pragma unroll
    for (int it = 0; it < 2; it++) {
        int i = tid + it * 128;
        int xr = i >> 3, xd = (i & 7) << 2;
        *(float4*)&Xs[0][xr][xd] = *(const float4*)(X + (size_t)(r0 + xr) * DQ + xd);
    }
    #pragma unroll
    for (int it = 0; it < 4; it++) {
        int i = tid + it * 128;
        int dd = i >> 4, c = (i & 15) << 2;
        *(float4*)&Ws[0][dd][c] = *(const float4*)(W + (size_t)dd * H + c0 + c);
    }
    __syncthreads();

    for (int ch = 0; ch < 8; ch++) {
        int cur = ch & 1;
        float4 px[2], pw[4];
        if (ch < 7) {
            int d0 = (ch + 1) * 32;
            #pragma unroll
            for (int it = 0; it < 2; it++) {
                int i = tid + it * 128;
                int xr = i >> 3, xd = (i & 7) << 2;
                px[it] = *(const float4*)(X + (size_t)(r0 + xr) * DQ + d0 + xd);
            }
            #pragma unroll
            for (int it = 0; it < 4; it++) {
                int i = tid + it * 128;
                int dd = i >> 4, c = (i & 15) << 2;
                pw[it] = *(const float4*)(W + (size_t)(d0 + dd) * H + c0 + c);
            }
        }

        #pragma unroll
        for (int dd = 0; dd < 32; dd += 4) {
            float4 xrg[4], wv[4];
            #pragma unroll
            for (int i = 0; i < 4; i++)
                xrg[i] = *(const float4*)&Xs[cur][(ty << 2) + i][dd];  // broadcast
            #pragma unroll
            for (int j = 0; j < 4; j++)
                wv[j] = *(const float4*)&Ws[cur][dd + j][tx << 2];
            #pragma unroll
            for (int i = 0; i < 4; i++) {
                float xi[4] = {xrg[i].x, xrg[i].y, xrg[i].z, xrg[i].w};
                #pragma unroll
                for (int j = 0; j < 4; j++) {
                    acc[i][0] = fmaf(xi[j], wv[j].x, acc[i][0]);
                    acc[i][1] = fmaf(xi[j], wv[j].y, acc[i][1]);
                    acc[i][2] = fmaf(xi[j], wv[j].z, acc[i][2]);
                    acc[i][3] = fmaf(xi[j], wv[j].w, acc[i][3]);
                }
            }
        }

        if (ch < 7) {
            int nxt = cur ^ 1;
            #pragma unroll
            for (int it = 0; it < 2; it++) {
                int i = tid + it * 128;
                int xr = i >> 3, xd = (i & 7) << 2;
                *(float4*)&Xs[nxt][xr][xd] = px[it];
            }
            #pragma unroll
            for (int it = 0; it < 4; it++) {
                int i = tid + it * 128;
                int dd = i >> 4, c = (i & 15) << 2;
                *(float4*)&Ws[nxt][dd][c] = pw[it];
            }
            __syncthreads();
        }
    }

    #pragma unroll
    for (int i = 0; i < 4; i++) {
        float4 v = make_float4(acc[i][0], acc[i][1], acc[i][2], acc[i][3]);
        *(float4*)(Y + (size_t)(r0 + (ty << 2) + i) * H + c0 + (tx << 2)) = v;
    }
}

// ---------------------------------------------------------------------------
// Kernel 2 (FUSED): scores + single-pass softmax-exp + AV partial.
// No max subtraction needed: |score| <= sum|w_h| (~9), exp cannot overflow,
// so exp(s)/sum(exp(s)) bit-matches within fp tolerance (validated R7-R9).
// Work item = (b, qtile32, ktile32) with ktile < ceil(vl/32); work-stealing
// over persistent CTAs. Per item: full-h q/k tiles staged once, 32x32 scores
// (MUFU-paced), p=exp masked, row-sums -> g_plsum, then P(32x32)@V(32x128)
// -> race-free per-ktile partial in g_part. AV + V-L2 traffic hides under
// the tanh MUFU floor.
// ---------------------------------------------------------------------------
__global__ __launch_bounds__(256) void fused_kernel(
    const float* __restrict__ values, const float* __restrict__ wv_g,
    const int* __restrict__ valid)
{
    __shared__ float qs[32][132];   // [q][h] full 128-h tile (pad->stride 4 mod 32)
    __shared__ float ks[128][33];   // [h][k] transposed
    __shared__ float Vs[32][128];   // V chunk for AV
    __shared__ float Ps[32][33];    // probabilities
    __shared__ float wvs[H];
    __shared__ unsigned int s_item;

    int tid = threadIdx.x;
    if (tid < H) wvs[tid] = wv_g[tid];

    int nk[BATCH], vls[BATCH], off[BATCH + 1];
    off[0] = 0;
    #pragma unroll
    for (int b = 0; b < BATCH; b++) {
        vls[b] = valid[b];
        nk[b] = (vls[b] + 31) >> 5;
        off[b + 1] = off[b] + 8 * nk[b];
    }
    unsigned int total = (unsigned int)off[BATCH];

    int tx = tid & 15;      // 2 keys at 2*tx
    int ty = tid >> 4;      // 2 queries at 2*ty
    int vx = tid & 31;      // AV: 4 v-cols at 4*vx
    int vy = tid >> 5;      // AV: 4 q-rows at 4*vy

    while (true) {
        __syncthreads();                      // item separation (smem reuse)
        if (tid == 0) s_item = atomicAdd(&g_ctr, 1u);
        __syncthreads();
        unsigned int w = s_item;
        if (w >= total) break;

        int b = 0;
        #pragma unroll
        for (int bb = 0; bb < BATCH - 1; bb++)
            if (w >= (unsigned int)off[bb + 1]) b = bb + 1;
        int idx   = (int)w - off[b];
        int ktile = idx % nk[b];
        int qtile = idx / nk[b];
        int k0 = ktile << 5, q0 = qtile << 5;
        int vl = vls[b];

        const float* qbase = g_qh + ((size_t)b * QLEN + q0) * H;
        const float* kbase = g_kh + ((size_t)b * KLEN + k0) * H;

        // ---- stage V early (latency hidden behind score phase) ----
        #pragma unroll
        for (int it = 0; it < 4; it++) {
            int i = tid + it * 256;            // 1024 float4s
            int vr = i >> 5, vc = (i & 31) << 2;
            *(float4*)&Vs[vr][vc] =
                *(const float4*)(values + ((size_t)b * KLEN + k0 + vr) * DV + vc);
        }
        // ---- stage full q tile [32][128] and k tile transposed [128][32] ----
        #pragma unroll
        for (int it = 0; it < 4; it++) {
            int i = tid + it * 256;            // 1024 float4s
            int r = i >> 5, hv = (i & 31) << 2;
            float4 v = *(const float4*)(qbase + (size_t)r * H + hv);
            *(float4*)&qs[r][hv] = v;
            float4 u = *(const float4*)(kbase + (size_t)r * H + hv);
            ks[hv + 0][r] = u.x; ks[hv + 1][r] = u.y;
            ks[hv + 2][r] = u.z; ks[hv + 3][r] = u.w;
        }
        __syncthreads();

        // ---- scores: 2x2 per thread over 128 h (MUFU-paced) ----
        float acc[2][2] = {};
        #pragma unroll 8
        for (int hh = 0; hh < H; hh++) {
            float w0 = wvs[hh];
            float qa = qs[(ty << 1) + 0][hh];
            float qb = qs[(ty << 1) + 1][hh];
            float ka = ks[hh][(tx << 1) + 0];
            float kb = ks[hh][(tx << 1) + 1];
            acc[0][0] = fmaf(w0, fast_tanh(qa + ka), acc[0][0]);
            acc[0][1] = fmaf(w0, fast_tanh(qa + kb), acc[0][1]);
            acc[1][0] = fmaf(w0, fast_tanh(qb + ka), acc[1][0]);
            acc[1][1] = fmaf(w0, fast_tanh(qb + kb), acc[1][1]);
        }

        // ---- p = exp(s), masked beyond valid_len ----
        int kg = k0 + (tx << 1);
        float p00 = (kg + 0 < vl) ? __expf(acc[0][0]) : 0.f;
        float p01 = (kg + 1 < vl) ? __expf(acc[0][1]) : 0.f;
        float p10 = (kg + 0 < vl) ? __expf(acc[1][0]) : 0.f;
        float p11 = (kg + 1 < vl) ? __expf(acc[1][1]) : 0.f;

        // ---- row sums across tx (16-lane groups) -> g_plsum ----
        float rs0 = p00 + p01, rs1 = p10 + p11;
        #pragma unroll
        for (int o = 8; o; o >>= 1) {
            rs0 += __shfl_xor_sync(0xffffffffu, rs0, o);
            rs1 += __shfl_xor_sync(0xffffffffu, rs1, o);
        }
        if ((tid & 15) == 0) {
            int q = q0 + (ty << 1);
            *(float2*)&g_plsum[(((ktile << 3) + b) << 8) + q] = make_float2(rs0, rs1);
        }

        // ---- stage P, then AV GEMM ----
        Ps[(ty << 1) + 0][(tx << 1) + 0] = p00;
        Ps[(ty << 1) + 0][(tx << 1) + 1] = p01;
        Ps[(ty << 1) + 1][(tx << 1) + 0] = p10;
        Ps[(ty << 1) + 1][(tx << 1) + 1] = p11;
        __syncthreads();

        float av[4][4] = {};
        #pragma unroll 8
        for (int kk = 0; kk < 32; kk++) {
            float4 vv = *(const float4*)&Vs[kk][vx << 2];
            #pragma unroll
            for (int i = 0; i < 4; i++) {
                float p = Ps[(vy << 2) + i][kk];      // warp-uniform broadcast
                av[i][0] = fmaf(p, vv.x, av[i][0]);
                av[i][1] = fmaf(p, vv.y, av[i][1]);
                av[i][2] = fmaf(p, vv.z, av[i][2]);
                av[i][3] = fmaf(p, vv.w, av[i][3]);
            }
        }

        float* pbase = g_part +
            ((((size_t)(ktile << 3) + b) << 8) + q0 + (vy << 2)) * DV + (vx << 2);
        #pragma unroll
        for (int i = 0; i < 4; i++)
            *(float4*)(pbase + (size_t)i * DV) =
                make_float4(av[i][0], av[i][1], av[i][2], av[i][3]);
    }
}

// ---------------------------------------------------------------------------
// Kernel 3: combine partials. out[b,q,v] = sum_kt part / sum_kt lsum.
// 2048 blocks x 128 threads (one thread per v-col).
// ---------------------------------------------------------------------------
__global__ __launch_bounds__(128) void combine_kernel(
    const int* __restrict__ valid, float* __restrict__ out)
{
    int bq  = blockIdx.x;            // b*256 + q
    int b   = bq >> 8;
    int q   = bq & 255;
    int nkt = (valid[b] + 31) >> 5;
    int tid = threadIdx.x;

    float o = 0.f, l = 0.f;
    for (int kt = 0; kt < nkt; kt++) {
        int slot = ((kt << 3) + b) << 8;
        o += g_part[((size_t)slot + q) * DV + tid];
        l += g_plsum[slot + q];
    }
    out[(size_t)bq * DV + tid] = o / l;
}

// ---------------------------------------------------------------------------
extern "C" void kernel_launch(void* const* d_in, const int* in_sizes, int n_in,
                              void* d_out, int out_size)
{
    const float* queries = (const float*)d_in[0];
    const float* keys    = (const float*)d_in[1];
    const float* values  = (const float*)d_in[2];
    const int*   valid   = (const int*)d_in[3];
    const float* Wq      = (const float*)d_in[4];
    const float* Wk      = (const float*)d_in[5];
    const float* wv      = (const float*)d_in[6];
    float* out = (float*)d_out;

    proj_kernel<<<640, 128>>>(queries, keys, Wq, Wk);
    fused_kernel<<<296, 256>>>(values, wv, valid);
    combine_kernel<<<BATCH * QLEN, 128>>>(valid, out);
}

// round 15
// speedup vs baseline: 1.2099x; 1.2099x over previous
#include <cuda_runtime.h>
#include <math.h>

#define BATCH 8
#define QLEN 256
#define KLEN 1024
#define DQ   256
#define DV   128
#define H    128

// Scratch (statically allocated device globals — no cudaMalloc).
__device__ float g_qh[BATCH * QLEN * H];          // 1 MB
__device__ float g_kh[BATCH * KLEN * H];          // 4 MB
__device__ float g_sc[BATCH * QLEN * KLEN];       // 8 MB
__device__ unsigned int g_ctr;                    // work-stealing counter

__device__ __forceinline__ float fast_tanh(float x) {
    float y;
    asm("tanh.approx.f32 %0, %1;" : "=f"(y) : "f"(x));
    return y;
}

// ---------------------------------------------------------------------------
// Kernel 1: fused projections qh = Q@Wq, kh = K@Wk.
// 32 output rows x 64 cols per block -> 640 blocks x 128 threads.
// K blocks whose 32 rows lie beyond ceil32(valid_len) are skipped: those kh
// rows are never read (scores only touches k-tiles < ceil(vl/32); tail rows
// inside the last tile feed only exp-masked entries, NaN-safe).
// 4x4 reg tile, double-buffered smem + register prefetch.
// ---------------------------------------------------------------------------
__global__ __launch_bounds__(128) void proj_kernel(
    const float* __restrict__ Qin, const float* __restrict__ Kin,
    const float* __restrict__ Wq,  const float* __restrict__ Wk,
    const int*   __restrict__ valid)
{
    if (blockIdx.x == 0 && threadIdx.x == 0) g_ctr = 0;  // reset for scores

    __shared__ float Xs[2][32][36];
    __shared__ float Ws[2][32][64];

    int blk = blockIdx.x;
    const float* X; const float* W; float* Y; int r0, c0;
    if (blk < 128) { X = Qin; W = Wq; Y = g_qh; r0 = (blk >> 1) * 32; c0 = (blk & 1) * 64; }
    else {
        int bb = blk - 128; X = Kin; W = Wk; Y = g_kh;
        r0 = (bb >> 1) * 32; c0 = (bb & 1) * 64;
        int b = r0 >> 10, kloc = r0 & 1023;
        if (kloc >= ((valid[b] + 31) & ~31)) return;     // kh rows never consumed
    }

    int tid = threadIdx.x;
    int tx = tid & 15;       // -> 4 cols at 4*tx
    int ty = tid >> 4;       // -> 4 rows at 4*ty

    float acc[4][4] = {};

    #pragma unroll
    for (int it = 0; it < 2; it++) {
        int i = tid + it * 128;
        int xr = i >> 3, xd = (i & 7) << 2;
        *(float4*)&Xs[0][xr][xd] = *(const float4*)(X + (size_t)(r0 + xr) * DQ + xd);
    }
    #pragma unroll
    for (int it = 0; it < 4; it++) {
        int i = tid + it * 128;
        int dd = i >> 4, c = (i & 15) << 2;
        *(float4*)&Ws[0][dd][c] = *(const float4*)(W + (size_t)dd * H + c0 + c);
    }
    __syncthreads();

    for (int ch = 0; ch < 8; ch++) {
        int cur = ch & 1;
        float4 px[2], pw[4];
        if (ch < 7) {
            int d0 = (ch + 1) * 32;
            #pragma unroll
            for (int it = 0; it < 2; it++) {
                int i = tid + it * 128;
                int xr = i >> 3, xd = (i & 7) << 2;
                px[it] = *(const float4*)(X + (size_t)(r0 + xr) * DQ + d0 + xd);
            }
            #pragma unroll
            for (int it = 0; it < 4; it++) {
                int i = tid + it * 128;
                int dd = i >> 4, c = (i & 15) << 2;
                pw[it] = *(const float4*)(W + (size_t)(d0 + dd) * H + c0 + c);
            }
        }

        #pragma unroll
        for (int dd = 0; dd < 32; dd += 4) {
            float4 xrg[4], wv[4];
            #pragma unroll
            for (int i = 0; i < 4; i++)
                xrg[i] = *(const float4*)&Xs[cur][(ty << 2) + i][dd];  // broadcast
            #pragma unroll
            for (int j = 0; j < 4; j++)
                wv[j] = *(const float4*)&Ws[cur][dd + j][tx << 2];
            #pragma unroll
            for (int i = 0; i < 4; i++) {
                float xi[4] = {xrg[i].x, xrg[i].y, xrg[i].z, xrg[i].w};
                #pragma unroll
                for (int j = 0; j < 4; j++) {
                    acc[i][0] = fmaf(xi[j], wv[j].x, acc[i][0]);
                    acc[i][1] = fmaf(xi[j], wv[j].y, acc[i][1]);
                    acc[i][2] = fmaf(xi[j], wv[j].z, acc[i][2]);
                    acc[i][3] = fmaf(xi[j], wv[j].w, acc[i][3]);
                }
            }
        }

        if (ch < 7) {
            int nxt = cur ^ 1;
            #pragma unroll
            for (int it = 0; it < 2; it++) {
                int i = tid + it * 128;
                int xr = i >> 3, xd = (i & 7) << 2;
                *(float4*)&Xs[nxt][xr][xd] = px[it];
            }
            #pragma unroll
            for (int it = 0; it < 4; it++) {
                int i = tid + it * 128;
                int dd = i >> 4, c = (i & 15) << 2;
                *(float4*)&Ws[nxt][dd][c] = pw[it];
            }
            __syncthreads();
        }
    }

    #pragma unroll
    for (int i = 0; i < 4; i++) {
        float4 v = make_float4(acc[i][0], acc[i][1], acc[i][2], acc[i][3]);
        *(float4*)(Y + (size_t)(r0 + (ty << 2) + i) * H + c0 + (tx << 2)) = v;
    }
}

// ---------------------------------------------------------------------------
// Kernel 2: scores[b,q,k] = sum_h w[h] * tanh(qh[b,q,h] + kh[b,k,h])
// 32q x 32k work items for k-tiles < valid_len, work-stealing over
// persistent CTAs. MUFU-bound near floor.
// ---------------------------------------------------------------------------
__global__ __launch_bounds__(256) void scores_kernel(
    const float* __restrict__ wv_g, const int* __restrict__ valid)
{
    __shared__ float qs[32][36];    // [q][h]  direct copy
    __shared__ float ks[32][33];    // [h][k]  transposed scatter
    __shared__ float wvs[H];
    __shared__ unsigned int s_item;

    int tid = threadIdx.x;
    if (tid < H) wvs[tid] = wv_g[tid];

    int nk[BATCH], off[BATCH + 1];
    off[0] = 0;
    #pragma unroll
    for (int b = 0; b < BATCH; b++) {
        nk[b] = (valid[b] + 31) >> 5;
        off[b + 1] = off[b] + 8 * nk[b];
    }
    unsigned int total = (unsigned int)off[BATCH];

    int tx = tid & 15;      // 2 keys at 2*tx
    int ty = tid >> 4;      // 2 queries at 2*ty

    while (true) {
        __syncthreads();                      // smem reuse + s_item protection
        if (tid == 0) s_item = atomicAdd(&g_ctr, 1u);
        __syncthreads();
        unsigned int w = s_item;
        if (w >= total) break;

        int b = 0;
        #pragma unroll
        for (int bb = 0; bb < BATCH - 1; bb++)
            if (w >= (unsigned int)off[bb + 1]) b = bb + 1;
        int idx   = (int)w - off[b];
        int ktile = idx % nk[b];
        int qtile = idx / nk[b];
        int k0 = ktile << 5, q0 = qtile << 5;

        const float* qbase = g_qh + ((size_t)b * QLEN + q0) * H;
        const float* kbase = g_kh + ((size_t)b * KLEN + k0) * H;

        float acc[2][2] = {};

        for (int h0 = 0; h0 < H; h0 += 32) {
            __syncthreads();
            {
                int r = tid >> 3, hv = (tid & 7) << 2;
                float4 v = *(const float4*)(qbase + (size_t)r * H + h0 + hv);
                *(float4*)&qs[r][hv] = v;
                float4 u = *(const float4*)(kbase + (size_t)r * H + h0 + hv);
                ks[hv + 0][r] = u.x; ks[hv + 1][r] = u.y;
                ks[hv + 2][r] = u.z; ks[hv + 3][r] = u.w;
            }
            __syncthreads();

            #pragma unroll
            for (int hh = 0; hh < 32; hh++) {
                float w0 = wvs[h0 + hh];
                float qa = qs[(ty << 1) + 0][hh];
                float qb = qs[(ty << 1) + 1][hh];
                float ka = ks[hh][(tx << 1) + 0];
                float kb = ks[hh][(tx << 1) + 1];
                acc[0][0] = fmaf(w0, fast_tanh(qa + ka), acc[0][0]);
                acc[0][1] = fmaf(w0, fast_tanh(qa + kb), acc[0][1]);
                acc[1][0] = fmaf(w0, fast_tanh(qb + ka), acc[1][0]);
                acc[1][1] = fmaf(w0, fast_tanh(qb + kb), acc[1][1]);
            }
        }

        float* s0 = g_sc + ((size_t)b * QLEN + q0 + (ty << 1)) * KLEN + k0 + (tx << 1);
        *(float2*)s0          = make_float2(acc[0][0], acc[0][1]);
        *(float2*)(s0 + KLEN) = make_float2(acc[1][0], acc[1][1]);
    }
}

// ---------------------------------------------------------------------------
// Kernel 3: fused softmax + AV, SINGLE PASS, no max subtraction.
// |score| <= sum_h |w_h| (~9) since tanh in [-1,1], so exp() cannot overflow
// fp32 and exp(s)/sum(exp(s)) == reference's max-subtracted softmax.
// 8 q-rows x 64 v-cols per CTA: grid (32 qtiles x 2 halves, 8 b) = 512 CTAs.
// 64-k chunks, double-buffered V+P smem with register prefetch (one sync per
// chunk). Row sums accumulated during P staging.
// ---------------------------------------------------------------------------
__global__ __launch_bounds__(256) void softmax_av_kernel(
    const float* __restrict__ values, const int* __restrict__ valid,
    float* __restrict__ out)
{
    __shared__ float Vs[2][64][64];   // 32 KB double-buffered V half-chunk
    __shared__ float Ps[2][8][64];    // 4 KB probabilities
    __shared__ float sm_li[8];

    int b    = blockIdx.y;
    int q0   = (blockIdx.x >> 1) << 3;
    int half = blockIdx.x & 1;
    int vl   = valid[b];
    int tid  = threadIdx.x;
    int lane = tid & 31, warp = tid >> 5;

    int tx = tid & 15;            // 4 v-cols at 4*tx (within half)
    int ty = tid >> 4;            // 16-way k split, 4 k each
    const float* vbase = values + (size_t)b * KLEN * DV + half * 64;

    int prow = tid >> 4, pk = (tid & 15) << 2;    // P staging (tid<128)
    const float* sbase = g_sc + ((size_t)b * QLEN + q0) * KLEN;

    float acc[8][4] = {};
    float lsum = 0.f;
    int nch = (vl + 63) >> 6;

    // ---- prologue: stage chunk 0 ----
    if (tid < 128) {
        float4 s4 = *(const float4*)(sbase + (size_t)prow * KLEN + pk);
        float4 p4;
        p4.x = (pk + 0 < vl) ? __expf(s4.x) : 0.f;
        p4.y = (pk + 1 < vl) ? __expf(s4.y) : 0.f;
        p4.z = (pk + 2 < vl) ? __expf(s4.z) : 0.f;
        p4.w = (pk + 3 < vl) ? __expf(s4.w) : 0.f;
        lsum += p4.x + p4.y + p4.z + p4.w;
        *(float4*)&Ps[0][prow][pk] = p4;
    }
    #pragma unroll
    for (int it = 0; it < 4; it++) {
        int i = tid + it * 256;
        int vr = i >> 4, vc = (i & 15) << 2;
        *(float4*)&Vs[0][vr][vc] = *(const float4*)(vbase + (size_t)vr * DV + vc);
    }
    __syncthreads();

    for (int ch = 0; ch < nch; ch++) {
        int cur = ch & 1, nxt = cur ^ 1;
        bool more = (ch + 1 < nch);
        int k1 = (ch + 1) << 6;

        // prefetch next chunk into registers
        float4 ps4, pv[4];
        if (more) {
            if (tid < 128)
                ps4 = *(const float4*)(sbase + (size_t)prow * KLEN + k1 + pk);
            #pragma unroll
            for (int it = 0; it < 4; it++) {
                int i = tid + it * 256;
                int vr = i >> 4, vc = (i & 15) << 2;
                pv[it] = *(const float4*)(vbase + (size_t)(k1 + vr) * DV + vc);
            }
        }

        // load P rows for this thread's k-group as float4 (8 LDS.128)
        float pr[8][4];
        #pragma unroll
        for (int r = 0; r < 8; r++) {
            float4 t = *(const float4*)&Ps[cur][r][ty << 2];
            pr[r][0] = t.x; pr[r][1] = t.y; pr[r][2] = t.z; pr[r][3] = t.w;
        }

        #pragma unroll
        for (int kks = 0; kks < 4; kks++) {
            float4 vv = *(const float4*)&Vs[cur][(ty << 2) + kks][tx << 2];
            #pragma unroll
            for (int r = 0; r < 8; r++) {
                float p = pr[r][kks];
                acc[r][0] = fmaf(p, vv.x, acc[r][0]);
                acc[r][1] = fmaf(p, vv.y, acc[r][1]);
                acc[r][2] = fmaf(p, vv.z, acc[r][2]);
                acc[r][3] = fmaf(p, vv.w, acc[r][3]);
            }
        }

        if (more) {
            if (tid < 128) {
                float4 p4;
                p4.x = (k1 + pk + 0 < vl) ? __expf(ps4.x) : 0.f;
                p4.y = (k1 + pk + 1 < vl) ? __expf(ps4.y) : 0.f;
                p4.z = (k1 + pk + 2 < vl) ? __expf(ps4.z) : 0.f;
                p4.w = (k1 + pk + 3 < vl) ? __expf(ps4.w) : 0.f;
                lsum += p4.x + p4.y + p4.z + p4.w;
                *(float4*)&Ps[nxt][prow][pk] = p4;
            }
            #pragma unroll
            for (int it = 0; it < 4; it++) {
                int i = tid + it * 256;
                int vr = i >> 4, vc = (i & 15) << 2;
                *(float4*)&Vs[nxt][vr][vc] = pv[it];
            }
        }
        __syncthreads();
    }

    // ---- row-sum reduction (16-lane groups of staging threads) ----
    #pragma unroll
    for (int o = 8; o; o >>= 1) lsum += __shfl_xor_sync(0xffffffffu, lsum, o);
    if (tid < 128 && (lane & 15) == 0) sm_li[prow] = 1.0f / lsum;

    // ---- acc reduction: shfl (ty pair within warp), then 8-way smem ----
    #pragma unroll
    for (int r = 0; r < 8; r++)
        #pragma unroll
        for (int j = 0; j < 4; j++)
            acc[r][j] += __shfl_xor_sync(0xffffffffu, acc[r][j], 16);

    __syncthreads();                          // Vs/Ps reuse + sm_li visible
    float4* red = (float4*)&Vs[0][0][0];      // [r][warp][cx] : 8*8*16 float4
    if (lane < 16) {
        #pragma unroll
        for (int r = 0; r < 8; r++)
            red[(r * 8 + warp) * 16 + lane] =
                make_float4(acc[r][0], acc[r][1], acc[r][2], acc[r][3]);
    }
    __syncthreads();
    if (tid < 128) {
        int r = tid >> 4, cx = tid & 15;
        float4 s = make_float4(0.f, 0.f, 0.f, 0.f);
        #pragma unroll
        for (int g = 0; g < 8; g++) {
            float4 t = red[(r * 8 + g) * 16 + cx];
            s.x += t.x; s.y += t.y; s.z += t.z; s.w += t.w;
        }
        float inv = sm_li[r];
        s.x *= inv; s.y *= inv; s.z *= inv; s.w *= inv;
        *(float4*)(out + ((size_t)b * QLEN + q0 + r) * DV + half * 64 + (cx << 2)) = s;
    }
}

// ---------------------------------------------------------------------------
extern "C" void kernel_launch(void* const* d_in, const int* in_sizes, int n_in,
                              void* d_out, int out_size)
{
    const float* queries = (const float*)d_in[0];
    const float* keys    = (const float*)d_in[1];
    const float* values  = (const float*)d_in[2];
    const int*   valid   = (const int*)d_in[3];
    const float* Wq      = (const float*)d_in[4];
    const float* Wk      = (const float*)d_in[5];
    const float* wv      = (const float*)d_in[6];
    float* out = (float*)d_out;

    proj_kernel<<<640, 128>>>(queries, keys, Wq, Wk, valid);
    scores_kernel<<<296, 256>>>(wv, valid);
    softmax_av_kernel<<<dim3(64, 8), 256>>>(values, valid, out);
}